// round 7
// baseline (speedup 1.0000x reference)
#include <cuda_runtime.h>

typedef unsigned long long ull;

// ---------------- problem constants ----------------
#define BATCH   128
#define HH      384
#define WW      384
#define OW      385
#define SH      58
#define STRIPS  7
#define NPART   (STRIPS*BATCH)
#define NTHREADS 224        // 7 warps; thread t owns cols 2t, 2t+1

// ---------------- shared layout (ull units) ----------------
#define RAW_ULL  3200
#define R7_ULL   5600
#define ZERO_ULL (RAW_ULL + R7_ULL)
#define SMEM_BYTES ((ZERO_ULL + 18) * 8)

__device__ float g_part[NPART * 5];

// ---------------- packed f32x2 helpers ----------------
__device__ __forceinline__ ull f2pack(float lo, float hi) {
    ull r; asm("mov.b64 %0,{%1,%2};" : "=l"(r) : "f"(lo), "f"(hi)); return r;
}
__device__ __forceinline__ void f2unpack(ull v, float& lo, float& hi) {
    asm("mov.b64 {%0,%1},%2;" : "=f"(lo), "=f"(hi) : "l"(v));
}
__device__ __forceinline__ float f2lo(ull v) { float lo, hi; f2unpack(v, lo, hi); return lo; }
__device__ __forceinline__ float f2hi(ull v) { float lo, hi; f2unpack(v, lo, hi); return hi; }
__device__ __forceinline__ ull f2add(ull a, ull b) {
    ull r; asm("add.rn.f32x2 %0,%1,%2;" : "=l"(r) : "l"(a), "l"(b)); return r;
}
__device__ __forceinline__ ull f2mul(ull a, ull b) {
    ull r; asm("mul.rn.f32x2 %0,%1,%2;" : "=l"(r) : "l"(a), "l"(b)); return r;
}
__device__ __forceinline__ ull f2fma(ull a, ull b, ull c) {
    ull r; asm("fma.rn.f32x2 %0,%1,%2,%3;" : "=l"(r) : "l"(a), "l"(b), "l"(c)); return r;
}
#define F2NEG1 0xBF800000BF800000ULL   // (-1.0f, -1.0f)

__device__ __forceinline__ float hadd(ull v) { float lo, hi; f2unpack(v, lo, hi); return lo + hi; }

// Vectorized SSIM over two columns (lanes). Q = Sxx+Syy per lane.
// Returns S_lane0 + S_lane1 with a single divide; msk zeroes invalid lanes.
__device__ __forceinline__ float ssim2(ull SX, ull SY, ull QQ, ull XY,
                                       ull nn, ull c1p, ull c2p, ull twop, ull msk)
{
    ull T  = f2mul(SX, SY);
    ull A1 = f2fma(twop, T, c1p);
    ull U  = f2fma(nn, XY, f2mul(T, F2NEG1));      // n*xy - t
    ull A2 = f2fma(twop, U, c2p);
    ull PQ = f2fma(SY, SY, f2mul(SX, SX));
    ull B1 = f2add(PQ, c1p);
    ull B2 = f2add(f2fma(nn, QQ, f2mul(PQ, F2NEG1)), c2p);
    ull N  = f2mul(f2mul(A1, A2), msk);
    ull D  = f2mul(B1, B2);
    float n0, n1, d0, d1;
    f2unpack(N, n0, n1); f2unpack(D, d0, d1);
    return __fdividef(fmaf(n0, d1, n1 * d0), d0 * d1);
}

__global__ __launch_bounds__(NTHREADS, 3)
void msssim_main_kernel(const float* __restrict__ X,
                        const float* __restrict__ Y,
                        const float* __restrict__ DR)
{
    extern __shared__ ull sm8[];
    ull*        raw = sm8;                         // [8][400]
    ulonglong2* r7  = (ulonglong2*)(sm8 + RAW_ULL);// [7][400]
    float*      red = (float*)(sm8 + ZERO_ULL);

    const int tid = threadIdx.x;
    const int b   = blockIdx.y;
    const int i0  = blockIdx.x * SH;
    const int i1  = min(i0 + SH, OW);
    const int i1k = min(i1, HH);
    const int ibase = i0 - 6;
    const int M   = i1 - ibase;
    const int nQuad = (M + 3) >> 2;

    const float dr = DR[b];
    const float C1 = (0.01f * dr) * (0.01f * dr);
    const float C2 = (0.03f * dr) * (0.03f * dr);

    // packed per-level constants (uniform across block)
    const ull TWOP  = f2pack(2.f, 2.f);
    const ull ONEP  = f2pack(1.f, 1.f);
    const ull C1P   = f2pack(C1, C1);
    const ull NN2   = f2pack(4.f, 4.f);
    const ull C12P  = f2pack(C1 * 16.f, C1 * 16.f);
    const ull C22P  = f2pack(C2 * 16.f, C2 * 16.f);
    const ull NN4   = f2pack(16.f, 16.f);
    const ull C14P  = f2pack(C1 * 256.f, C1 * 256.f);
    const ull C24P  = f2pack(C2 * 256.f, C2 * 256.f);
    const ull NN7   = f2pack(49.f, 49.f);
    const ull C17P  = f2pack(C1 * 2401.f, C1 * 2401.f);
    const ull C27P  = f2pack(C2 * 2401.f, C2 * 2401.f);

    // zero all ring smem
    for (int k = tid; k < ZERO_ULL; k += NTHREADS) sm8[k] = 0ULL;

    const int  t    = tid;
    const bool act  = (t < 193);
    const bool full = (t < 192);
    const ull  lmsk = full ? ONEP : f2pack(1.f, 0.f);   // lane mask for k2/k4

    // h4 register ring
    ull h4s0[4], h4m0[4], h4s1[4], h4m1[4];
    #pragma unroll
    for (int q = 0; q < 4; ++q) { h4s0[q]=0; h4m0[q]=0; h4s1[q]=0; h4m1[q]=0; }

    ull v7s0 = 0, v7m0 = 0, v7s1 = 0, v7m1 = 0;
    float acc1 = 0.f, acc2 = 0.f, acc4 = 0.f, acc7 = 0.f, accL = 0.f;
    int s7i = 0;

    const float2* X2 = (const float2*)X + (size_t)b * (HH * WW / 2);
    const float2* Y2 = (const float2*)Y + (size_t)b * (HH * WW / 2);

    float2 zz; zz.x = 0.f; zz.y = 0.f;
    float2 xA = zz, yA = zz, xB = zz, yB = zz;
    if (full) {
        int rA = ibase + 3;
        if ((unsigned)rA < HH) { xA = X2[rA * 192 + t]; yA = Y2[rA * 192 + t]; }
        if ((unsigned)(rA + 1) < HH) { xB = X2[(rA + 1) * 192 + t]; yB = Y2[(rA + 1) * 192 + t]; }
    }
    __syncthreads();

    // prefetch r7 old values for the first iteration (zeros; thread-private data)
    ulonglong2 pf0, pf1;
    pf0.x = 0; pf0.y = 0; pf1.x = 0; pf1.y = 0;
    if (act) { pf0 = r7[t]; pf1 = r7[200 + t]; }

    for (int mo = 0; mo < nQuad; ++mo) {
        #pragma unroll
        for (int up = 0; up < 2; ++up) {
            const int m0 = (mo << 2) + (up << 1);

            float2 xpA = zz, ypA = zz, xpB = zz, ypB = zz;
            if (full) {
                int rn = ibase + m0 + 5;
                if ((unsigned)rn < HH) { xpA = X2[rn * 192 + t]; ypA = Y2[rn * 192 + t]; }
                if ((unsigned)(rn + 1) < HH) { xpB = X2[(rn+1) * 192 + t]; ypB = Y2[(rn+1) * 192 + t]; }
            }
            if (full) {
                ull* pa = raw + (m0 & 7) * 400;
                pa[t + 2]       = f2pack(xA.x, yA.x);
                pa[200 + t + 2] = f2pack(xA.y, yA.y);
                ull* pb = raw + ((m0 + 1) & 7) * 400;
                pb[t + 2]       = f2pack(xB.x, yB.x);
                pb[200 + t + 2] = f2pack(xB.y, yB.y);
            }
            __syncthreads();

            #pragma unroll
            for (int s = 0; s < 2; ++s) {
                const int m  = m0 + s;
                const int t4 = (up << 1) + s;
                const int i  = ibase + m;
                const int r  = i + 3;
                const float2 xc = s ? xB : xA;
                const float2 yc = s ? yB : yA;

                // ---- k=1 SSIM for row r (vectorized over 2 pixels) ----
                if (full && r >= i0 && r < i1k) {
                    ull PX = f2pack(xc.x, xc.y), PY = f2pack(yc.x, yc.y);
                    ull T  = f2mul(PX, PY);
                    ull A  = f2fma(TWOP, T, C1P);
                    ull B  = f2fma(PX, PX, f2fma(PY, PY, C1P));
                    float a0, a1, b0, b1;
                    f2unpack(A, a0, a1); f2unpack(B, b0, b1);
                    acc1 += __fdividef(fmaf(a0, b1, a1 * b0), b0 * b1);
                }

                if (act) {
                    // ---- h7 for row r, v7 slide (prefetched old values) ----
                    {
                        const ull* eb = raw + (m & 7) * 400;
                        ull o_m2 = eb[200 + t],     e_m1 = eb[t + 1],
                            o_m1 = eb[200 + t + 1], e0   = eb[t + 2],
                            o0   = eb[200 + t + 2], e1   = eb[t + 3],
                            o1   = eb[200 + t + 3], e2   = eb[t + 4];
                        float xa,ya,xb2,yb2,xcv,ycv,xd,yd,xe,ye,xf,yf,xg,yg,xh,yh;
                        f2unpack(o_m2,xa,ya);  f2unpack(e_m1,xb2,yb2);
                        f2unpack(o_m1,xcv,ycv); f2unpack(e0,xd,yd);
                        f2unpack(o0,xe,ye);    f2unpack(e1,xf,yf);
                        f2unpack(o1,xg,yg);    f2unpack(e2,xh,yh);

                        ull s7 = f2add(f2add(f2add(o_m2, e_m1), f2add(o_m1, e0)),
                                       f2add(f2add(o0, e1), o1));
                        ull sq7 = f2fma(o_m2,o_m2, f2fma(e_m1,e_m1, f2fma(o_m1,o_m1,
                                  f2fma(e0,e0, f2fma(o0,o0, f2fma(e1,e1, f2mul(o1,o1)))))));
                        float Q7  = hadd(sq7);
                        float xy7 = fmaf(xa,ya, fmaf(xb2,yb2, fmaf(xcv,ycv,
                                    fmaf(xd,yd, fmaf(xe,ye, fmaf(xf,yf, xg*yg))))));
                        ull   s7b = f2add(f2fma(o_m2, F2NEG1, s7), e2);
                        float Q7b = Q7 - fmaf(xa,xa, ya*ya) + fmaf(xh,xh, yh*yh);
                        float xy7b = fmaf(xh, yh, fmaf(-xa, ya, xy7));
                        ull m7  = f2pack(Q7,  xy7);
                        ull m7b = f2pack(Q7b, xy7b);

                        ulonglong2* rp = r7 + s7i * 400 + t;
                        ulonglong2 nv; nv.x = s7; nv.y = m7; rp[0] = nv;
                        nv.x = s7b; nv.y = m7b; rp[200] = nv;
                        v7s0 = f2fma(pf0.x, F2NEG1, f2add(v7s0, s7));
                        v7m0 = f2fma(pf0.y, F2NEG1, f2add(v7m0, m7));
                        v7s1 = f2fma(pf1.x, F2NEG1, f2add(v7s1, s7b));
                        v7m1 = f2fma(pf1.y, F2NEG1, f2add(v7m1, m7b));

                        s7i = (s7i == 6) ? 0 : s7i + 1;
                        ulonglong2* rq = r7 + s7i * 400 + t;
                        pf0 = rq[0]; pf1 = rq[200];        // prefetch next old
                    }

                    // ---- h4 for row i+1 -> reg ring slot t4 ----
                    {
                        const ull* fb = raw + ((m + 6) & 7) * 400;
                        ull e_m1 = fb[t + 1], o_m1 = fb[200 + t + 1],
                            e0   = fb[t + 2], o0   = fb[200 + t + 2],
                            e1   = fb[t + 3];
                        float xa,ya,xb2,yb2,xcv,ycv,xd,yd,xe,ye;
                        f2unpack(e_m1,xa,ya); f2unpack(o_m1,xb2,yb2);
                        f2unpack(e0,xcv,ycv); f2unpack(o0,xd,yd);
                        f2unpack(e1,xe,ye);
                        ull s4 = f2add(f2add(e_m1, o_m1), f2add(e0, o0));
                        ull sq4 = f2fma(e_m1,e_m1, f2fma(o_m1,o_m1,
                                  f2fma(e0,e0, f2mul(o0,o0))));
                        float Q4  = hadd(sq4);
                        float xy4 = fmaf(xa,ya, fmaf(xb2,yb2, fmaf(xcv,ycv, xd*yd)));
                        h4s0[t4] = s4;
                        h4m0[t4] = f2pack(Q4, xy4);
                        ull   s4b = f2add(f2fma(e_m1, F2NEG1, s4), e1);
                        float Q4b = Q4 - fmaf(xa,xa, ya*ya) + fmaf(xe,xe, ye*ye);
                        float xy4b = fmaf(xe, ye, fmaf(-xa, ya, xy4));
                        h4s1[t4] = s4b;
                        h4m1[t4] = f2pack(Q4b, xy4b);
                    }

                    // ---- emit output row i ----
                    if (i >= i0 && i < i1) {
                        // k=2 direct from raw rows i-1, i
                        const ull* ra_ = raw + ((m + 4) & 7) * 400;
                        const ull* rb_ = raw + ((m + 5) & 7) * 400;
                        ull a_om1 = ra_[200 + t + 1], a_e0 = ra_[t + 2], a_o0 = ra_[200 + t + 2];
                        ull b_om1 = rb_[200 + t + 1], b_e0 = rb_[t + 2], b_o0 = rb_[200 + t + 2];
                        float axa,aya,axb,ayb,axc,ayc,bxa,bya,bxb,byb,bxc,byc;
                        f2unpack(a_om1,axa,aya); f2unpack(a_e0,axb,ayb); f2unpack(a_o0,axc,ayc);
                        f2unpack(b_om1,bxa,bya); f2unpack(b_e0,bxb,byb); f2unpack(b_o0,bxc,byc);

                        ull s2 = f2add(f2add(a_om1, a_e0), f2add(b_om1, b_e0));
                        ull sq2 = f2fma(a_om1,a_om1, f2fma(a_e0,a_e0,
                                  f2fma(b_om1,b_om1, f2mul(b_e0,b_e0))));
                        float Q20  = hadd(sq2);
                        float xy20 = fmaf(axa,aya, fmaf(axb,ayb, fmaf(bxa,bya, bxb*byb)));
                        ull s2b = f2add(f2add(a_e0, a_o0), f2add(b_e0, b_o0));
                        ull sq2b = f2fma(a_e0,a_e0, f2fma(a_o0,a_o0,
                                   f2fma(b_e0,b_e0, f2mul(b_o0,b_o0))));
                        float Q21  = hadd(sq2b);
                        float xy21 = fmaf(axb,ayb, fmaf(axc,ayc, fmaf(bxb,byb, bxc*byc)));

                        acc2 += ssim2(f2pack(f2lo(s2), f2lo(s2b)),
                                      f2pack(f2hi(s2), f2hi(s2b)),
                                      f2pack(Q20, Q21), f2pack(xy20, xy21),
                                      NN2, C12P, C22P, TWOP, lmsk);

                        // k=4 resum
                        ull ss0 = f2add(f2add(h4s0[0], h4s0[1]), f2add(h4s0[2], h4s0[3]));
                        ull mm0 = f2add(f2add(h4m0[0], h4m0[1]), f2add(h4m0[2], h4m0[3]));
                        ull ss1 = f2add(f2add(h4s1[0], h4s1[1]), f2add(h4s1[2], h4s1[3]));
                        ull mm1 = f2add(f2add(h4m1[0], h4m1[1]), f2add(h4m1[2], h4m1[3]));
                        acc4 += ssim2(f2pack(f2lo(ss0), f2lo(ss1)),
                                      f2pack(f2hi(ss0), f2hi(ss1)),
                                      f2pack(f2lo(mm0), f2lo(mm1)),
                                      f2pack(f2hi(mm0), f2hi(mm1)),
                                      NN4, C14P, C24P, TWOP, lmsk);

                        if (full && i < HH) {
                            acc7 += ssim2(f2pack(f2lo(v7s0), f2lo(v7s1)),
                                          f2pack(f2hi(v7s0), f2hi(v7s1)),
                                          f2pack(f2lo(v7m0), f2lo(v7m1)),
                                          f2pack(f2hi(v7m0), f2hi(v7m1)),
                                          NN7, C17P, C27P, TWOP, ONEP);
                            accL += fabsf(f2lo(v7s0) - f2hi(v7s0))
                                  + fabsf(f2lo(v7s1) - f2hi(v7s1));
                        }
                    }
                }
            }
            xA = xpA; yA = ypA; xB = xpB; yB = ypB;
        }
    }

    // ---------------- deterministic block reduction ----------------
    #pragma unroll
    for (int o = 16; o > 0; o >>= 1) {
        acc1 += __shfl_down_sync(0xFFFFFFFFu, acc1, o);
        acc2 += __shfl_down_sync(0xFFFFFFFFu, acc2, o);
        acc4 += __shfl_down_sync(0xFFFFFFFFu, acc4, o);
        acc7 += __shfl_down_sync(0xFFFFFFFFu, acc7, o);
        accL += __shfl_down_sync(0xFFFFFFFFu, accL, o);
    }
    __syncthreads();
    const int w = tid >> 5, lane = tid & 31;
    if (lane == 0) {
        red[w*5 + 0] = acc1; red[w*5 + 1] = acc2; red[w*5 + 2] = acc4;
        red[w*5 + 3] = acc7; red[w*5 + 4] = accL;
    }
    __syncthreads();
    if (tid == 0) {
        float s0 = 0.f, s1 = 0.f, s2 = 0.f, s3 = 0.f, s4 = 0.f;
        for (int ww = 0; ww < 7; ++ww) {
            s0 += red[ww*5 + 0]; s1 += red[ww*5 + 1]; s2 += red[ww*5 + 2];
            s3 += red[ww*5 + 3]; s4 += red[ww*5 + 4];
        }
        const int pb = (b * STRIPS + blockIdx.x) * 5;
        g_part[pb + 0] = s0; g_part[pb + 1] = s1; g_part[pb + 2] = s2;
        g_part[pb + 3] = s3; g_part[pb + 4] = s4;
    }
}

__global__ void msssim_reduce_kernel(float* __restrict__ out)
{
    __shared__ double red[256][5];
    double a0 = 0, a1 = 0, a2 = 0, a3 = 0, a4 = 0;
    for (int idx = threadIdx.x; idx < NPART; idx += 256) {
        a0 += (double)g_part[idx*5 + 0];
        a1 += (double)g_part[idx*5 + 1];
        a2 += (double)g_part[idx*5 + 2];
        a3 += (double)g_part[idx*5 + 3];
        a4 += (double)g_part[idx*5 + 4];
    }
    red[threadIdx.x][0] = a0; red[threadIdx.x][1] = a1; red[threadIdx.x][2] = a2;
    red[threadIdx.x][3] = a3; red[threadIdx.x][4] = a4;
    __syncthreads();
    for (int s = 128; s > 0; s >>= 1) {
        if (threadIdx.x < s) {
            #pragma unroll
            for (int q = 0; q < 5; ++q) red[threadIdx.x][q] += red[threadIdx.x + s][q];
        }
        __syncthreads();
    }
    if (threadIdx.x == 0) {
        const double n384 = (double)BATCH * 384.0 * 384.0;
        const double n385 = (double)BATCH * 385.0 * 385.0;
        double m1 = red[0][0] / n384;
        double m2 = red[0][1] / n385;
        double m4 = red[0][2] / n385;
        double m7 = red[0][3] / n384;
        double l1 = red[0][4] / (49.0 * n384);
        double loss = 0.84 * (1.0 - m1 * m2 * m4 * m7) + 0.16 * l1;
        out[0] = (float)loss;
    }
}

// one pad launch keeps ncu's "-s 5 -c 1" landing on the MAIN kernel
__global__ void msssim_noop_kernel() {}

extern "C" void kernel_launch(void* const* d_in, const int* in_sizes, int n_in,
                              void* d_out, int out_size)
{
    (void)in_sizes; (void)n_in; (void)out_size;
    const float* X  = (const float*)d_in[0];
    const float* Y  = (const float*)d_in[1];
    const float* DR = (const float*)d_in[2];

    cudaFuncSetAttribute(msssim_main_kernel,
                         cudaFuncAttributeMaxDynamicSharedMemorySize, SMEM_BYTES);

    dim3 grid(STRIPS, BATCH);
    msssim_main_kernel<<<grid, NTHREADS, SMEM_BYTES>>>(X, Y, DR);
    msssim_reduce_kernel<<<1, 256>>>((float*)d_out);
    msssim_noop_kernel<<<1, 32>>>();
}

// round 8
// speedup vs baseline: 1.0363x; 1.0363x over previous
#include <cuda_runtime.h>

typedef unsigned long long ull;

// ---------------- problem constants ----------------
#define BATCH   128
#define HH      384
#define WW      384
#define OW      385
#define SH      58
#define STRIPS  7
#define NPART   (STRIPS*BATCH)
#define NTHREADS 224        // 7 warps; thread t owns cols 2t, 2t+1

// ---------------- shared layout (ull units) ----------------
#define RAW_ULL  3200
#define R7_ULL   5600
#define ZERO_ULL (RAW_ULL + R7_ULL)
#define SMEM_BYTES ((ZERO_ULL + 18) * 8)

__device__ float g_part[NPART * 5];

// ---------------- packed f32x2 helpers ----------------
__device__ __forceinline__ ull f2pack(float lo, float hi) {
    ull r; asm("mov.b64 %0,{%1,%2};" : "=l"(r) : "f"(lo), "f"(hi)); return r;
}
__device__ __forceinline__ void f2unpack(ull v, float& lo, float& hi) {
    asm("mov.b64 {%0,%1},%2;" : "=f"(lo), "=f"(hi) : "l"(v));
}
__device__ __forceinline__ ull f2add(ull a, ull b) {
    ull r; asm("add.rn.f32x2 %0,%1,%2;" : "=l"(r) : "l"(a), "l"(b)); return r;
}
__device__ __forceinline__ ull f2mul(ull a, ull b) {
    ull r; asm("mul.rn.f32x2 %0,%1,%2;" : "=l"(r) : "l"(a), "l"(b)); return r;
}
__device__ __forceinline__ ull f2fma(ull a, ull b, ull c) {
    ull r; asm("fma.rn.f32x2 %0,%1,%2,%3;" : "=l"(r) : "l"(a), "l"(b), "l"(c)); return r;
}
#define F2NEG1 0xBF800000BF800000ULL   // (-1.0f, -1.0f)

__device__ __forceinline__ float hadd(ull v) { float lo, hi; f2unpack(v, lo, hi); return lo + hi; }

// SSIM numerator/denominator (scalar; Q = Sxx+Syy). n=k*k, c1=C1*n^2, c2=C2*n^2.
__device__ __forceinline__ float ssim_nd(float Sx, float Sy, float Q, float xy,
                                         float n, float c1, float c2, float& D)
{
    float t  = Sx * Sy;
    float A1 = fmaf(2.f, t, c1);
    float u  = fmaf(n, xy, -t);
    float A2 = fmaf(2.f, u, c2);
    float pq = fmaf(Sy, Sy, Sx * Sx);
    float B1 = pq + c1;
    float B2 = fmaf(n, Q, -pq) + c2;
    D = B1 * B2;
    return A1 * A2;
}

__global__ __launch_bounds__(NTHREADS, 3)
void msssim_main_kernel(const float* __restrict__ X,
                        const float* __restrict__ Y,
                        const float* __restrict__ DR)
{
    extern __shared__ ull sm8[];
    ull*        raw = sm8;                          // [8][400]
    ulonglong2* r7  = (ulonglong2*)(sm8 + RAW_ULL); // [7][400]
    float*      red = (float*)(sm8 + ZERO_ULL);

    const int tid = threadIdx.x;
    const int b   = blockIdx.y;
    const int i0  = blockIdx.x * SH;
    const int i1  = min(i0 + SH, OW);
    const int i1k = min(i1, HH);
    const int ibase = i0 - 6;
    const int M   = i1 - ibase;                     // 64 (43 last strip)
    const int nOct = (M + 7) >> 3;                  // groups of 8 rows

    const float dr = DR[b];
    const float C1 = (0.01f * dr) * (0.01f * dr);
    const float C2 = (0.03f * dr) * (0.03f * dr);
    const float c1_2 = C1 * 16.f,   c2_2 = C2 * 16.f;
    const float c1_4 = C1 * 256.f,  c2_4 = C2 * 256.f;
    const float c1_7 = C1 * 2401.f, c2_7 = C2 * 2401.f;

    // zero all ring smem
    for (int k = tid; k < ZERO_ULL; k += NTHREADS) sm8[k] = 0ULL;

    const int  t    = tid;
    const bool act  = (t < 193);
    const bool full = (t < 192);
    const float msk1 = full ? 1.f : 0.f;    // col j1 validity for k2/k4

    // h4 register ring (4 slots, 2 cols)
    ull h4s0[4], h4m0[4], h4s1[4], h4m1[4];
    #pragma unroll
    for (int q = 0; q < 4; ++q) { h4s0[q]=0; h4m0[q]=0; h4s1[q]=0; h4m1[q]=0; }

    ull v7s0 = 0, v7m0 = 0, v7s1 = 0, v7m1 = 0;
    float acc1 = 0.f, acc2 = 0.f, acc4 = 0.f, acc7 = 0.f, accL = 0.f;
    int s7i = 0;

    const float2* X2 = (const float2*)X + (size_t)b * (HH * WW / 2);
    const float2* Y2 = (const float2*)Y + (size_t)b * (HH * WW / 2);

    float2 zz; zz.x = 0.f; zz.y = 0.f;
    // current batch rows (4) — rows ibase+3 .. ibase+6 initially
    float2 cx[4], cy[4];
    #pragma unroll
    for (int s = 0; s < 4; ++s) {
        cx[s] = zz; cy[s] = zz;
        int rr = ibase + 3 + s;
        if (full && (unsigned)rr < HH) { cx[s] = X2[rr * 192 + t]; cy[s] = Y2[rr * 192 + t]; }
    }
    __syncthreads();

    for (int mo = 0; mo < nOct; ++mo) {
        #pragma unroll
        for (int up = 0; up < 2; ++up) {
            const int m0 = (mo << 3) + (up << 2);   // batch start; m0&7 == up*4
            const int S0 = up << 2;                 // compile-time slot base

            // prefetch next batch rows (ibase+m0+7 .. +10)
            float2 px[4], py[4];
            #pragma unroll
            for (int s = 0; s < 4; ++s) {
                px[s] = zz; py[s] = zz;
                int rr = ibase + m0 + 7 + s;
                if (full && (unsigned)rr < HH) { px[s] = X2[rr * 192 + t]; py[s] = Y2[rr * 192 + t]; }
            }
            // store current batch rows into ring slots S0..S0+3
            if (full) {
                #pragma unroll
                for (int s = 0; s < 4; ++s) {
                    int rr = ibase + m0 + 3 + s;
                    if ((unsigned)rr < HH) {
                        ull* pa = raw + (S0 + s) * 400;
                        pa[t + 2]       = f2pack(cx[s].x, cy[s].x);
                        pa[200 + t + 2] = f2pack(cx[s].y, cy[s].y);
                    }
                }
            }
            __syncthreads();

            #pragma unroll
            for (int s = 0; s < 4; ++s) {
                const int m = m0 + s;
                const int i = ibase + m;
                const int r = i + 3;

                if (act) {
                    // ---- h7 for row r (slot S0+s), k=1 folded in ----
                    {
                        const ull* eb = raw + (S0 + s) * 400;
                        ull o_m2 = eb[200 + t],     e_m1 = eb[t + 1],
                            o_m1 = eb[200 + t + 1], e0   = eb[t + 2],
                            o0   = eb[200 + t + 2], e1   = eb[t + 3],
                            o1   = eb[200 + t + 3], e2   = eb[t + 4];
                        float xa,ya,xb2,yb2,xcv,ycv,xd,yd,xe,ye,xf,yf,xg,yg,xh,yh;
                        f2unpack(o_m2,xa,ya);  f2unpack(e_m1,xb2,yb2);
                        f2unpack(o_m1,xcv,ycv); f2unpack(e0,xd,yd);
                        f2unpack(o0,xe,ye);    f2unpack(e1,xf,yf);
                        f2unpack(o1,xg,yg);    f2unpack(e2,xh,yh);

                        // k=1 SSIM for row r (cols 2t, 2t+1), one divide
                        if (full && r >= i0 && r < i1k) {
                            float t0 = xd * yd;
                            float a0 = fmaf(2.f, t0, C1);
                            float b0 = fmaf(xd, xd, fmaf(yd, yd, C1));
                            float t1 = xe * ye;
                            float a1 = fmaf(2.f, t1, C1);
                            float b1 = fmaf(xe, xe, fmaf(ye, ye, C1));
                            acc1 += __fdividef(fmaf(a0, b1, a1 * b0), b0 * b1);
                        }

                        ull s7 = f2add(f2add(f2add(o_m2, e_m1), f2add(o_m1, e0)),
                                       f2add(f2add(o0, e1), o1));
                        ull sq7 = f2fma(o_m2,o_m2, f2fma(e_m1,e_m1, f2fma(o_m1,o_m1,
                                  f2fma(e0,e0, f2fma(o0,o0, f2fma(e1,e1, f2mul(o1,o1)))))));
                        float Q7  = hadd(sq7);
                        float xy7 = fmaf(xa,ya, fmaf(xb2,yb2, fmaf(xcv,ycv,
                                    fmaf(xd,yd, fmaf(xe,ye, fmaf(xf,yf, xg*yg))))));
                        ull   s7b = f2add(f2fma(o_m2, F2NEG1, s7), e2);
                        float Q7b = Q7 - fmaf(xa,xa, ya*ya) + fmaf(xh,xh, yh*yh);
                        float xy7b = fmaf(xh, yh, fmaf(-xa, ya, xy7));
                        ull m7  = f2pack(Q7,  xy7);
                        ull m7b = f2pack(Q7b, xy7b);

                        ulonglong2* rp = r7 + s7i * 400 + t;
                        ulonglong2 o0v = rp[0];
                        ulonglong2 nv; nv.x = s7; nv.y = m7; rp[0] = nv;
                        v7s0 = f2fma(o0v.x, F2NEG1, f2add(v7s0, s7));
                        v7m0 = f2fma(o0v.y, F2NEG1, f2add(v7m0, m7));
                        ulonglong2 o1v = rp[200];
                        nv.x = s7b; nv.y = m7b; rp[200] = nv;
                        v7s1 = f2fma(o1v.x, F2NEG1, f2add(v7s1, s7b));
                        v7m1 = f2fma(o1v.y, F2NEG1, f2add(v7m1, m7b));
                        s7i = (s7i == 6) ? 0 : s7i + 1;
                    }

                    // ---- h4 for row i+1 (slot (S0+s+6)&7) -> reg ring slot s ----
                    {
                        const ull* fb = raw + ((S0 + s + 6) & 7) * 400;
                        ull e_m1 = fb[t + 1], o_m1 = fb[200 + t + 1],
                            e0   = fb[t + 2], o0   = fb[200 + t + 2],
                            e1   = fb[t + 3];
                        float xa,ya,xb2,yb2,xcv,ycv,xd,yd,xe,ye;
                        f2unpack(e_m1,xa,ya); f2unpack(o_m1,xb2,yb2);
                        f2unpack(e0,xcv,ycv); f2unpack(o0,xd,yd);
                        f2unpack(e1,xe,ye);
                        ull s4 = f2add(f2add(e_m1, o_m1), f2add(e0, o0));
                        ull sq4 = f2fma(e_m1,e_m1, f2fma(o_m1,o_m1,
                                  f2fma(e0,e0, f2mul(o0,o0))));
                        float Q4  = hadd(sq4);
                        float xy4 = fmaf(xa,ya, fmaf(xb2,yb2, fmaf(xcv,ycv, xd*yd)));
                        h4s0[s] = s4;
                        h4m0[s] = f2pack(Q4, xy4);
                        ull   s4b = f2add(f2fma(e_m1, F2NEG1, s4), e1);
                        float Q4b = Q4 - fmaf(xa,xa, ya*ya) + fmaf(xe,xe, ye*ye);
                        float xy4b = fmaf(xe, ye, fmaf(-xa, ya, xy4));
                        h4s1[s] = s4b;
                        h4m1[s] = f2pack(Q4b, xy4b);
                    }

                    // ---- emit output row i ----
                    if (i >= i0 && i < i1) {
                        float Sx, Sy, D0, D1;
                        // k=2 direct from raw rows i-1 (slot (S0+s+4)&7), i ((S0+s+5)&7)
                        const ull* ra_ = raw + ((S0 + s + 4) & 7) * 400;
                        const ull* rb_ = raw + ((S0 + s + 5) & 7) * 400;
                        ull a_om1 = ra_[200 + t + 1], a_e0 = ra_[t + 2], a_o0 = ra_[200 + t + 2];
                        ull b_om1 = rb_[200 + t + 1], b_e0 = rb_[t + 2], b_o0 = rb_[200 + t + 2];
                        float axa,aya,axb,ayb,axc,ayc,bxa,bya,bxb,byb,bxc,byc;
                        f2unpack(a_om1,axa,aya); f2unpack(a_e0,axb,ayb); f2unpack(a_o0,axc,ayc);
                        f2unpack(b_om1,bxa,bya); f2unpack(b_e0,bxb,byb); f2unpack(b_o0,bxc,byc);

                        ull s2 = f2add(f2add(a_om1, a_e0), f2add(b_om1, b_e0));
                        ull sq2 = f2fma(a_om1,a_om1, f2fma(a_e0,a_e0,
                                  f2fma(b_om1,b_om1, f2mul(b_e0,b_e0))));
                        float Q20  = hadd(sq2);
                        float xy20 = fmaf(axa,aya, fmaf(axb,ayb, fmaf(bxa,bya, bxb*byb)));
                        ull s2b = f2add(f2add(a_e0, a_o0), f2add(b_e0, b_o0));
                        ull sq2b = f2fma(a_e0,a_e0, f2fma(a_o0,a_o0,
                                   f2fma(b_e0,b_e0, f2mul(b_o0,b_o0))));
                        float Q21  = hadd(sq2b);
                        float xy21 = fmaf(axb,ayb, fmaf(axc,ayc, fmaf(bxb,byb, bxc*byc)));

                        f2unpack(s2, Sx, Sy);
                        float N0 = ssim_nd(Sx, Sy, Q20, xy20, 4.f, c1_2, c2_2, D0);
                        f2unpack(s2b, Sx, Sy);
                        float N1 = ssim_nd(Sx, Sy, Q21, xy21, 4.f, c1_2, c2_2, D1) * msk1;
                        acc2 += __fdividef(fmaf(N0, D1, N1 * D0), D0 * D1);

                        // k=4 resum of reg ring
                        ull ss = f2add(f2add(h4s0[0], h4s0[1]), f2add(h4s0[2], h4s0[3]));
                        ull mm = f2add(f2add(h4m0[0], h4m0[1]), f2add(h4m0[2], h4m0[3]));
                        float Qv, xyv;
                        f2unpack(ss, Sx, Sy); f2unpack(mm, Qv, xyv);
                        N0 = ssim_nd(Sx, Sy, Qv, xyv, 16.f, c1_4, c2_4, D0);
                        ss = f2add(f2add(h4s1[0], h4s1[1]), f2add(h4s1[2], h4s1[3]));
                        mm = f2add(f2add(h4m1[0], h4m1[1]), f2add(h4m1[2], h4m1[3]));
                        f2unpack(ss, Sx, Sy); f2unpack(mm, Qv, xyv);
                        N1 = ssim_nd(Sx, Sy, Qv, xyv, 16.f, c1_4, c2_4, D1) * msk1;
                        acc4 += __fdividef(fmaf(N0, D1, N1 * D0), D0 * D1);

                        if (full && i < HH) {
                            f2unpack(v7s0, Sx, Sy); f2unpack(v7m0, Qv, xyv);
                            N0 = ssim_nd(Sx, Sy, Qv, xyv, 49.f, c1_7, c2_7, D0);
                            accL += fabsf(Sx - Sy);
                            f2unpack(v7s1, Sx, Sy); f2unpack(v7m1, Qv, xyv);
                            N1 = ssim_nd(Sx, Sy, Qv, xyv, 49.f, c1_7, c2_7, D1);
                            accL += fabsf(Sx - Sy);
                            acc7 += __fdividef(fmaf(N0, D1, N1 * D0), D0 * D1);
                        }
                    }
                }
            }
            #pragma unroll
            for (int s = 0; s < 4; ++s) { cx[s] = px[s]; cy[s] = py[s]; }
        }
    }

    // ---------------- deterministic block reduction ----------------
    #pragma unroll
    for (int o = 16; o > 0; o >>= 1) {
        acc1 += __shfl_down_sync(0xFFFFFFFFu, acc1, o);
        acc2 += __shfl_down_sync(0xFFFFFFFFu, acc2, o);
        acc4 += __shfl_down_sync(0xFFFFFFFFu, acc4, o);
        acc7 += __shfl_down_sync(0xFFFFFFFFu, acc7, o);
        accL += __shfl_down_sync(0xFFFFFFFFu, accL, o);
    }
    __syncthreads();
    const int w = tid >> 5, lane = tid & 31;
    if (lane == 0) {
        red[w*5 + 0] = acc1; red[w*5 + 1] = acc2; red[w*5 + 2] = acc4;
        red[w*5 + 3] = acc7; red[w*5 + 4] = accL;
    }
    __syncthreads();
    if (tid == 0) {
        float s0 = 0.f, s1 = 0.f, s2 = 0.f, s3 = 0.f, s4 = 0.f;
        for (int ww = 0; ww < 7; ++ww) {
            s0 += red[ww*5 + 0]; s1 += red[ww*5 + 1]; s2 += red[ww*5 + 2];
            s3 += red[ww*5 + 3]; s4 += red[ww*5 + 4];
        }
        const int pb = (b * STRIPS + blockIdx.x) * 5;
        g_part[pb + 0] = s0; g_part[pb + 1] = s1; g_part[pb + 2] = s2;
        g_part[pb + 3] = s3; g_part[pb + 4] = s4;
    }
}

__global__ void msssim_reduce_kernel(float* __restrict__ out)
{
    __shared__ double red[256][5];
    double a0 = 0, a1 = 0, a2 = 0, a3 = 0, a4 = 0;
    for (int idx = threadIdx.x; idx < NPART; idx += 256) {
        a0 += (double)g_part[idx*5 + 0];
        a1 += (double)g_part[idx*5 + 1];
        a2 += (double)g_part[idx*5 + 2];
        a3 += (double)g_part[idx*5 + 3];
        a4 += (double)g_part[idx*5 + 4];
    }
    red[threadIdx.x][0] = a0; red[threadIdx.x][1] = a1; red[threadIdx.x][2] = a2;
    red[threadIdx.x][3] = a3; red[threadIdx.x][4] = a4;
    __syncthreads();
    for (int s = 128; s > 0; s >>= 1) {
        if (threadIdx.x < s) {
            #pragma unroll
            for (int q = 0; q < 5; ++q) red[threadIdx.x][q] += red[threadIdx.x + s][q];
        }
        __syncthreads();
    }
    if (threadIdx.x == 0) {
        const double n384 = (double)BATCH * 384.0 * 384.0;
        const double n385 = (double)BATCH * 385.0 * 385.0;
        double m1 = red[0][0] / n384;
        double m2 = red[0][1] / n385;
        double m4 = red[0][2] / n385;
        double m7 = red[0][3] / n384;
        double l1 = red[0][4] / (49.0 * n384);
        double loss = 0.84 * (1.0 - m1 * m2 * m4 * m7) + 0.16 * l1;
        out[0] = (float)loss;
    }
}

// one pad launch keeps ncu's "-s 5 -c 1" landing on the MAIN kernel
__global__ void msssim_noop_kernel() {}

extern "C" void kernel_launch(void* const* d_in, const int* in_sizes, int n_in,
                              void* d_out, int out_size)
{
    (void)in_sizes; (void)n_in; (void)out_size;
    const float* X  = (const float*)d_in[0];
    const float* Y  = (const float*)d_in[1];
    const float* DR = (const float*)d_in[2];

    cudaFuncSetAttribute(msssim_main_kernel,
                         cudaFuncAttributeMaxDynamicSharedMemorySize, SMEM_BYTES);

    dim3 grid(STRIPS, BATCH);
    msssim_main_kernel<<<grid, NTHREADS, SMEM_BYTES>>>(X, Y, DR);
    msssim_reduce_kernel<<<1, 256>>>((float*)d_out);
    msssim_noop_kernel<<<1, 32>>>();
}